// round 13
// baseline (speedup 1.0000x reference)
#include <cuda_runtime.h>
#include <cuda_fp16.h>
#include <cstdint>

// VectorQuantizerRestart: z [16,128,4096] fp32, codebook [1024,128] fp32
#define D_DIM 128
#define T_DIM 4096
#define K_DIM 1024
#define N_TOK 65536

__device__ __align__(16) float g_cnorm[K_DIM];
// split-K candidates: [half 2][token]
__device__ float g_cv[2 * N_TOK];
__device__ int   g_ci[2 * N_TOK];
// fp16 2-limb codebook, fragment-ordered:
// [half2][chunk4][s8][limb2][ntp8][lane32][q4] uint32(f16x2)  (512 KB)
__device__ __align__(16) uint32_t g_bfrag[2 * 4 * 8 * 2 * 8 * 32 * 4];
// fp16 2-limb z tiles, fragment-ordered to match As exactly:
// [tile512][ (s8*8+mt8)*2+limb ][lane32] uint4  (32 MB)
__device__ __align__(16) uint4 g_afrag[512 * 4096];

__device__ __forceinline__ void split2(float x, unsigned short& h, unsigned short& m) {
    __half hh = __float2half_rn(x);
    float r = x - __half2float(hh);
    __half mm = __float2half_rn(r);
    h = __half_as_ushort(hh);
    m = __half_as_ushort(mm);
}

__device__ __forceinline__ void mma_f16(float* d, const uint32_t* a, const uint32_t* b) {
    asm volatile(
        "mma.sync.aligned.m16n8k16.row.col.f32.f16.f16.f32 "
        "{%0,%1,%2,%3}, {%4,%5,%6,%7}, {%8,%9}, {%0,%1,%2,%3};"
        : "+f"(d[0]), "+f"(d[1]), "+f"(d[2]), "+f"(d[3])
        : "r"(a[0]), "r"(a[1]), "r"(a[2]), "r"(a[3]), "r"(b[0]), "r"(b[1]));
}

// ---------------------------------------------------------------------------
// Fused pre-kernel: grid segments
//   [0, 4096)          A-frag split: thread = (tile, s, mt, lane), both limbs
//   [4096, 4608)       B-frag split (codebook)
//   [4608, 4736)       codebook norms (one warp per code)
// All three independent; argmin consumes their outputs.
// ---------------------------------------------------------------------------
#define PRE_A 4096
#define PRE_B 512
#define PRE_C 128

__global__ void vq_pre_kernel(const float* __restrict__ z, const float* __restrict__ cb) {
    int blk = blockIdx.x;
    int tid = threadIdx.x;

    if (blk < PRE_A) {
        // ---- A-frag: z -> 2 fp16 limbs in m16n8k16 fragment order
        int gidx = blk * 256 + tid;            // 1,048,576
        int lane = gidx & 31;
        int mt   = (gidx >> 5) & 7;
        int s    = (gidx >> 8) & 7;
        int tile = gidx >> 11;                 // 0..511
        int n0 = tile * 128;
        int bb = n0 >> 12;
        int t0 = n0 & (T_DIM - 1);
        const float* zb = z + (size_t)bb * D_DIM * T_DIM + t0;
        int m = mt * 16 + (lane >> 2);
        int k = s * 16 + (lane & 3) * 2;
        float xv[8];
        xv[0] = zb[(k    ) * T_DIM + m    ];  xv[1] = zb[(k + 1) * T_DIM + m    ];
        xv[2] = zb[(k    ) * T_DIM + m + 8];  xv[3] = zb[(k + 1) * T_DIM + m + 8];
        xv[4] = zb[(k + 8) * T_DIM + m    ];  xv[5] = zb[(k + 9) * T_DIM + m    ];
        xv[6] = zb[(k + 8) * T_DIM + m + 8];  xv[7] = zb[(k + 9) * T_DIM + m + 8];
        unsigned short hh[8], mm[8];
        #pragma unroll
        for (int i = 0; i < 8; i++) split2(xv[i], hh[i], mm[i]);
        uint4 hv, mv;
        hv.x = (uint32_t)hh[0] | ((uint32_t)hh[1] << 16);
        hv.y = (uint32_t)hh[2] | ((uint32_t)hh[3] << 16);
        hv.z = (uint32_t)hh[4] | ((uint32_t)hh[5] << 16);
        hv.w = (uint32_t)hh[6] | ((uint32_t)hh[7] << 16);
        mv.x = (uint32_t)mm[0] | ((uint32_t)mm[1] << 16);
        mv.y = (uint32_t)mm[2] | ((uint32_t)mm[3] << 16);
        mv.z = (uint32_t)mm[4] | ((uint32_t)mm[5] << 16);
        mv.w = (uint32_t)mm[6] | ((uint32_t)mm[7] << 16);
        size_t base = (size_t)tile * 4096 + (size_t)((s * 8 + mt) * 2) * 32 + lane;
        g_afrag[base]      = hv;
        g_afrag[base + 32] = mv;
    } else if (blk < PRE_A + PRE_B) {
        // ---- B-frag: codebook -> 2 fp16 limbs, fragment order
        int e = (blk - PRE_A) * 256 + tid;     // 131072
        int q    = e & 3;
        int lane = (e >> 2) & 31;
        int ntp  = (e >> 7) & 7;
        int limb = (e >> 10) & 1;
        int s    = (e >> 11) & 7;
        int chunk= (e >> 14) & 3;
        int half = (e >> 16) & 1;
        int n = half * 512 + chunk * 128 + (ntp * 2 + (q >> 1)) * 8 + (lane >> 2);
        int k = s * 16 + ((q & 1) << 3) + (lane & 3) * 2;
        float x0 = cb[n * D_DIM + k];
        float x1 = cb[n * D_DIM + k + 1];
        unsigned short h0, m0, h1, m1;
        split2(x0, h0, m0);
        split2(x1, h1, m1);
        unsigned short lo = (limb == 0) ? h0 : m0;
        unsigned short hi = (limb == 0) ? h1 : m1;
        g_bfrag[e] = (uint32_t)lo | ((uint32_t)hi << 16);
    } else {
        // ---- cnorm: one warp per code
        int w    = ((blk - PRE_A - PRE_B) * 256 + tid) >> 5;
        int lane = tid & 31;
        if (w >= K_DIM) return;
        float s = 0.f;
        #pragma unroll
        for (int d = lane; d < D_DIM; d += 32) {
            float v = cb[(size_t)w * D_DIM + d];
            s = fmaf(v, v, s);
        }
        #pragma unroll
        for (int o = 16; o > 0; o >>= 1) s += __shfl_xor_sync(0xffffffffu, s, o);
        if (lane == 0) g_cnorm[w] = s;
    }
}

// ---------------------------------------------------------------------------
// Kernel 2: 3-term fp16 2-limb mma.sync + register argmin, split-K over codes.
// grid = 1024: blockIdx = tile*2 + half; each CTA = 512 codes in 4 chunks of 128.
// CTA: 512 thr = 16 warps = 4 mg x 4 ng (4 warps/SMSP); warp tile m32 x n32.
// A now pre-split in gmem: prologue = flat 64KB cp.async in group 0 (A+cn+B0)
// — removes the serial in-CTA load/convert (~3k cyc/CTA, 2x duplicated).
// B double-buffered (2 x 64KB), single-sync pipeline.
// ---------------------------------------------------------------------------
#define A_U4   4096            // uint4: [s8][mt8][limb2][lane32]
#define B_U4   4096            // per buffer: [s8][limb2][ntp8][lane32]
#define SMEM_BYTES ((A_U4 + 2 * B_U4) * 16 + 512 * 4)   // 198656

__global__ __launch_bounds__(512, 1)
void vq_argmin_kernel(void) {
    extern __shared__ uint4 smem4[];
    uint4* As = smem4;
    uint4* Bs = smem4 + A_U4;
    float* cn = reinterpret_cast<float*>(smem4 + A_U4 + 2 * B_U4);

    const int tid  = threadIdx.x;
    const int lane = tid & 31;
    const int w    = tid >> 5;
    const int mg   = w >> 2;                 // 0..3  (m32 tile)
    const int ng   = w & 3;                  // 0..3  (n32 tile)

    const int tile = blockIdx.x >> 1;
    const int half = blockIdx.x & 1;
    const int n0 = tile * 128;
    const int kb0 = half * 512;

    const uint32_t asm0 = (uint32_t)__cvta_generic_to_shared(As);
    const uint32_t bsm  = (uint32_t)__cvta_generic_to_shared(Bs);
    const uint32_t cnsm = (uint32_t)__cvta_generic_to_shared(cn);
    const float4*  bsrc = reinterpret_cast<const float4*>(g_bfrag) + half * 4 * B_U4;
    const uint4*   asrc = g_afrag + (size_t)tile * A_U4;

    // ---- group 0: A tile (64KB) + cn (2KB) + B chunk 0 (64KB)
    #pragma unroll
    for (int i = 0; i < 8; ++i) {
        int e = i * 512 + tid;
        asm volatile("cp.async.cg.shared.global [%0], [%1], 16;"
                     :: "r"(asm0 + (uint32_t)e * 16u), "l"(asrc + e) : "memory");
    }
    if (tid < 128) {
        asm volatile("cp.async.ca.shared.global [%0], [%1], 16;"
                     :: "r"(cnsm + tid * 16u), "l"(g_cnorm + kb0 + tid * 4) : "memory");
    }
    #pragma unroll
    for (int i = 0; i < 8; ++i) {
        int e = i * 512 + tid;
        asm volatile("cp.async.cg.shared.global [%0], [%1], 16;"
                     :: "r"(bsm + (uint32_t)e * 16u), "l"(bsrc + e) : "memory");
    }
    asm volatile("cp.async.commit_group;" ::: "memory");

    float minv[4];                            // [mt][row-half]
    int   mini[4];
    #pragma unroll
    for (int j = 0; j < 4; j++) { minv[j] = 3.4e38f; mini[j] = 0; }

    static const int TLA[3] = {0, 0, 1};
    static const int TLB[3] = {0, 1, 0};

    #pragma unroll 1
    for (int c = 0; c < 4; ++c) {
        asm volatile("cp.async.wait_group 0;" ::: "memory");
        __syncthreads();     // buf[c&1]+A+cn visible; all done reading buf[(c+1)&1]

        if (c < 3) {         // prefetch c+1 into the buffer just freed
            int buf1 = (c + 1) & 1;
            const float4* src = bsrc + (c + 1) * B_U4;
            #pragma unroll
            for (int i = 0; i < 8; ++i) {
                int e = i * 512 + tid;
                asm volatile("cp.async.cg.shared.global [%0], [%1], 16;"
                             :: "r"(bsm + (uint32_t)(buf1 * B_U4 + e) * 16u),
                                "l"(src + e) : "memory");
            }
            asm volatile("cp.async.commit_group;" ::: "memory");
        }

        const uint4* Bb = Bs + (c & 1) * B_U4;
        float acc[2][4][4];                   // [mt][ntile][quad]
        #pragma unroll
        for (int mt = 0; mt < 2; mt++)
            #pragma unroll
            for (int nt = 0; nt < 4; nt++)
                #pragma unroll
                for (int qi = 0; qi < 4; qi++) acc[mt][nt][qi] = 0.f;

        #pragma unroll
        for (int s = 0; s < 8; ++s) {
            uint32_t afr[2][2][4];            // [mt][limb][4]
            #pragma unroll
            for (int mt = 0; mt < 2; mt++)
                #pragma unroll
                for (int limb = 0; limb < 2; limb++) {
                    uint4 v = As[((s * 8 + mg * 2 + mt) * 2 + limb) * 32 + lane];
                    afr[mt][limb][0] = v.x; afr[mt][limb][1] = v.y;
                    afr[mt][limb][2] = v.z; afr[mt][limb][3] = v.w;
                }
            uint32_t bfr[2][4][2];            // [limb][ntile][2 regs]
            #pragma unroll
            for (int limb = 0; limb < 2; limb++)
                #pragma unroll
                for (int np = 0; np < 2; np++) {
                    uint4 v = Bb[((s * 2 + limb) * 8 + ng * 2 + np) * 32 + lane];
                    bfr[limb][np * 2    ][0] = v.x; bfr[limb][np * 2    ][1] = v.y;
                    bfr[limb][np * 2 + 1][0] = v.z; bfr[limb][np * 2 + 1][1] = v.w;
                }
            // 3 terms: h*h, h*m, m*h (m*m ~ 2^-22 rel: negligible)
            #pragma unroll
            for (int term = 0; term < 3; term++) {
                const int la = TLA[term], lb = TLB[term];
                #pragma unroll
                for (int nt = 0; nt < 4; nt++)
                    #pragma unroll
                    for (int mt = 0; mt < 2; mt++)
                        mma_f16(acc[mt][nt], afr[mt][la], bfr[lb][nt]);
            }
        }

        // ---- epilogue: d2 = ||c||^2 - 2*dot, strict-< running min (n ascending)
        #pragma unroll
        for (int nt = 0; nt < 4; nt++) {
            int nl = c * 128 + ng * 32 + nt * 8 + 2 * (lane & 3);
            float cv0 = cn[nl], cv1 = cn[nl + 1];
            int n = kb0 + nl;
            #pragma unroll
            for (int mt = 0; mt < 2; mt++) {
                float d00 = fmaf(-2.f, acc[mt][nt][0], cv0);
                float d01 = fmaf(-2.f, acc[mt][nt][1], cv1);
                float d10 = fmaf(-2.f, acc[mt][nt][2], cv0);
                float d11 = fmaf(-2.f, acc[mt][nt][3], cv1);
                int j0 = mt * 2, j1 = mt * 2 + 1;
                if (d00 < minv[j0]) { minv[j0] = d00; mini[j0] = n; }
                if (d01 < minv[j0]) { minv[j0] = d01; mini[j0] = n + 1; }
                if (d10 < minv[j1]) { minv[j1] = d10; mini[j1] = n; }
                if (d11 < minv[j1]) { minv[j1] = d11; mini[j1] = n + 1; }
            }
        }
    }

    // ---- cross-thread reduce: 16 candidates per token -> g_cv/g_ci[half]
    __syncthreads();                          // all compute done before smem reuse
    float* rv = reinterpret_cast<float*>(smem4);          // [128][16]
    int*   ri = reinterpret_cast<int*>(rv + 2048);
    #pragma unroll
    for (int mt = 0; mt < 2; mt++)
        #pragma unroll
        for (int rh = 0; rh < 2; rh++) {
            int tok  = mg * 32 + mt * 16 + rh * 8 + (lane >> 2);
            int slot = ng * 4 + (lane & 3);
            rv[tok * 16 + slot] = minv[mt * 2 + rh];
            ri[tok * 16 + slot] = mini[mt * 2 + rh];
        }
    __syncthreads();
    if (tid < 128) {
        float bv = rv[tid * 16];
        int   bi = ri[tid * 16];
        #pragma unroll
        for (int x = 1; x < 16; x++) {
            float v = rv[tid * 16 + x];
            int   k = ri[tid * 16 + x];
            if (v < bv || (v == bv && k < bi)) { bv = v; bi = k; }
        }
        g_cv[half * N_TOK + n0 + tid] = bv;
        g_ci[half * N_TOK + n0 + tid] = bi;
    }
}

// ---------------------------------------------------------------------------
// Kernel 3: gather + split-K merge. Warp = 32 consecutive t, 8-wide d slice.
// half0 indices < half1, so half0 wins ties (first-min semantics).
// ---------------------------------------------------------------------------
__global__ void vq_gather_kernel(const float* __restrict__ cb, float* __restrict__ out) {
    int gw   = (blockIdx.x * blockDim.x + threadIdx.x) >> 5;   // 32768 warps
    int lane = threadIdx.x & 31;
    int t  = ((gw & 127) << 5) + lane;
    int d0 = ((gw >> 7) & 15) << 3;
    int b  = gw >> 11;
    int tg = b * T_DIM + t;
    float v0 = g_cv[tg], v1 = g_cv[N_TOK + tg];
    int idx = (v1 < v0) ? g_ci[N_TOK + tg] : g_ci[tg];
    const float4* src = reinterpret_cast<const float4*>(cb + (size_t)idx * D_DIM + d0);
    float4 w0 = __ldg(src);
    float4 w1 = __ldg(src + 1);
    size_t obase = ((size_t)b * D_DIM + d0) * T_DIM + t;
    out[obase + 0 * T_DIM] = w0.x;
    out[obase + 1 * T_DIM] = w0.y;
    out[obase + 2 * T_DIM] = w0.z;
    out[obase + 3 * T_DIM] = w0.w;
    out[obase + 4 * T_DIM] = w1.x;
    out[obase + 5 * T_DIM] = w1.y;
    out[obase + 6 * T_DIM] = w1.z;
    out[obase + 7 * T_DIM] = w1.w;
}

// ---------------------------------------------------------------------------
extern "C" void kernel_launch(void* const* d_in, const int* in_sizes, int n_in,
                              void* d_out, int out_size) {
    const float* z  = (const float*)d_in[0];
    const float* cb = (const float*)d_in[1];
    float* out = (float*)d_out;

    cudaFuncSetAttribute(vq_argmin_kernel,
                         cudaFuncAttributeMaxDynamicSharedMemorySize, SMEM_BYTES);

    vq_pre_kernel<<<PRE_A + PRE_B + PRE_C, 256>>>(z, cb);
    vq_argmin_kernel<<<(N_TOK / 128) * 2, 512, SMEM_BYTES>>>();
    vq_gather_kernel<<<4096, 256>>>(cb, out);
}

// round 14
// speedup vs baseline: 1.0417x; 1.0417x over previous
#include <cuda_runtime.h>
#include <cuda_fp16.h>
#include <cstdint>

// VectorQuantizerRestart: z [16,128,4096] fp32, codebook [1024,128] fp32
#define D_DIM 128
#define T_DIM 4096
#define K_DIM 1024
#define N_TOK 65536

__device__ __align__(16) float g_cnorm[K_DIM];
// split-K candidates: [half 2][token]
__device__ float g_cv[2 * N_TOK];
__device__ int   g_ci[2 * N_TOK];
// fp16 2-limb codebook, fragment-ordered:
// [half2][chunk4][s8][limb2][ntp8][lane32][q4] uint32(f16x2)  (512 KB)
__device__ __align__(16) uint32_t g_bfrag[2 * 4 * 8 * 2 * 8 * 32 * 4];

__device__ __forceinline__ void split2(float x, unsigned short& h, unsigned short& m) {
    __half hh = __float2half_rn(x);
    float r = x - __half2float(hh);
    __half mm = __float2half_rn(r);
    h = __half_as_ushort(hh);
    m = __half_as_ushort(mm);
}

__device__ __forceinline__ void mma_f16(float* d, const uint32_t* a, const uint32_t* b) {
    asm volatile(
        "mma.sync.aligned.m16n8k16.row.col.f32.f16.f16.f32 "
        "{%0,%1,%2,%3}, {%4,%5,%6,%7}, {%8,%9}, {%0,%1,%2,%3};"
        : "+f"(d[0]), "+f"(d[1]), "+f"(d[2]), "+f"(d[3])
        : "r"(a[0]), "r"(a[1]), "r"(a[2]), "r"(a[3]), "r"(b[0]), "r"(b[1]));
}

// ---------------------------------------------------------------------------
// Fused pre-kernel: blocks [0,512) = B-frag split, [512,640) = codebook norms.
// ---------------------------------------------------------------------------
__global__ void vq_pre_kernel(const float* __restrict__ cb) {
    int blk = blockIdx.x;
    int tid = threadIdx.x;

    if (blk < 512) {
        // ---- B-frag: codebook -> 2 fp16 limbs, m16n8k16 fragment order
        int e = blk * 256 + tid;               // 131072
        int q    = e & 3;
        int lane = (e >> 2) & 31;
        int ntp  = (e >> 7) & 7;
        int limb = (e >> 10) & 1;
        int s    = (e >> 11) & 7;
        int chunk= (e >> 14) & 3;
        int half = (e >> 16) & 1;
        int n = half * 512 + chunk * 128 + (ntp * 2 + (q >> 1)) * 8 + (lane >> 2);
        int k = s * 16 + ((q & 1) << 3) + (lane & 3) * 2;
        float x0 = cb[n * D_DIM + k];
        float x1 = cb[n * D_DIM + k + 1];
        unsigned short h0, m0, h1, m1;
        split2(x0, h0, m0);
        split2(x1, h1, m1);
        unsigned short lo = (limb == 0) ? h0 : m0;
        unsigned short hi = (limb == 0) ? h1 : m1;
        g_bfrag[e] = (uint32_t)lo | ((uint32_t)hi << 16);
    } else {
        // ---- cnorm: one warp per code
        int w    = ((blk - 512) * 256 + tid) >> 5;
        int lane = tid & 31;
        if (w >= K_DIM) return;
        float s = 0.f;
        #pragma unroll
        for (int d = lane; d < D_DIM; d += 32) {
            float v = cb[(size_t)w * D_DIM + d];
            s = fmaf(v, v, s);
        }
        #pragma unroll
        for (int o = 16; o > 0; o >>= 1) s += __shfl_xor_sync(0xffffffffu, s, o);
        if (lane == 0) g_cnorm[w] = s;
    }
}

// ---------------------------------------------------------------------------
// Kernel 2 (R10 config — session best): 3-term fp16 2-limb mma.sync + register
// argmin, split-K over codes. grid = 1024: blockIdx = tile*2 + half; each CTA
// = 512 codes in 4 chunks of 128. CTA: 512 thr = 16 warps = 8 mg x 2 ng;
// warp tile m16 x n64. A (64KB) resident; B double-buffered (2 x 64KB),
// single-sync pipeline; A-prologue hidden under the B0 cp.async wait.
// ---------------------------------------------------------------------------
#define A_U4   4096            // uint4: [s8][mt8][limb2][lane32]
#define B_U4   4096            // per buffer: [s8][limb2][ntp8][lane32]
#define SMEM_BYTES ((A_U4 + 2 * B_U4) * 16 + 512 * 4)   // 198656

__global__ __launch_bounds__(512, 1)
void vq_argmin_kernel(const float* __restrict__ z) {
    extern __shared__ uint4 smem4[];
    uint4* As = smem4;
    uint4* Bs = smem4 + A_U4;
    float* cn = reinterpret_cast<float*>(smem4 + A_U4 + 2 * B_U4);

    const int tid  = threadIdx.x;
    const int lane = tid & 31;
    const int w    = tid >> 5;
    const int mg   = w >> 1;                 // 0..7  (m16 tile)
    const int ng   = w & 1;                  // 0..1  (n64 tile)

    const int tile = blockIdx.x >> 1;
    const int half = blockIdx.x & 1;
    const int n0 = tile * 128;
    const int kb0 = half * 512;
    const int bb = n0 >> 12;
    const int t0 = n0 & (T_DIM - 1);
    const float* zb = z + (size_t)bb * D_DIM * T_DIM + t0;

    const uint32_t bsm = (uint32_t)__cvta_generic_to_shared(Bs);
    const uint32_t cnsm = (uint32_t)__cvta_generic_to_shared(cn);
    const float4*  bsrc = reinterpret_cast<const float4*>(g_bfrag) + half * 4 * B_U4;

    // ---- group 0: cn (2KB) + B chunk 0 (64KB) — overlaps the A-split below
    if (tid < 128) {
        asm volatile("cp.async.ca.shared.global [%0], [%1], 16;"
                     :: "r"(cnsm + tid * 16u), "l"(g_cnorm + kb0 + tid * 4) : "memory");
    }
    #pragma unroll
    for (int i = 0; i < 8; ++i) {
        int e = i * 512 + tid;
        asm volatile("cp.async.cg.shared.global [%0], [%1], 16;"
                     :: "r"(bsm + (uint32_t)e * 16u), "l"(bsrc + e) : "memory");
    }
    asm volatile("cp.async.commit_group;" ::: "memory");

    // ---- A prologue: z -> 2 fp16 limbs in m16n8k16 fragment order.
    for (int p = w; p < 64; p += 16) {
        int s  = p >> 3;
        int mt = p & 7;
        int m = mt * 16 + (lane >> 2);
        int k = s * 16 + (lane & 3) * 2;
        float xv[8];
        xv[0] = zb[(k    ) * T_DIM + m    ];  xv[1] = zb[(k + 1) * T_DIM + m    ];
        xv[2] = zb[(k    ) * T_DIM + m + 8];  xv[3] = zb[(k + 1) * T_DIM + m + 8];
        xv[4] = zb[(k + 8) * T_DIM + m    ];  xv[5] = zb[(k + 9) * T_DIM + m    ];
        xv[6] = zb[(k + 8) * T_DIM + m + 8];  xv[7] = zb[(k + 9) * T_DIM + m + 8];
        unsigned short hh[8], mm[8];
        #pragma unroll
        for (int i = 0; i < 8; i++) split2(xv[i], hh[i], mm[i]);
        #pragma unroll
        for (int limb = 0; limb < 2; limb++) {
            const unsigned short* u = (limb == 0) ? hh : mm;
            uint4 v;
            v.x = (uint32_t)u[0] | ((uint32_t)u[1] << 16);
            v.y = (uint32_t)u[2] | ((uint32_t)u[3] << 16);
            v.z = (uint32_t)u[4] | ((uint32_t)u[5] << 16);
            v.w = (uint32_t)u[6] | ((uint32_t)u[7] << 16);
            As[((s * 8 + mt) * 2 + limb) * 32 + lane] = v;
        }
    }

    float minv[2];
    int   mini[2];
    minv[0] = minv[1] = 3.4e38f;
    mini[0] = mini[1] = 0;

    static const int TLA[3] = {0, 0, 1};
    static const int TLB[3] = {0, 1, 0};

    #pragma unroll 1
    for (int c = 0; c < 4; ++c) {
        asm volatile("cp.async.wait_group 0;" ::: "memory");
        __syncthreads();     // buf[c&1]+A(+cn) visible; all done reading buf[(c+1)&1]

        if (c < 3) {         // prefetch c+1 into the buffer just freed
            int buf1 = (c + 1) & 1;
            const float4* src = bsrc + (c + 1) * B_U4;
            #pragma unroll
            for (int i = 0; i < 8; ++i) {
                int e = i * 512 + tid;
                asm volatile("cp.async.cg.shared.global [%0], [%1], 16;"
                             :: "r"(bsm + (uint32_t)(buf1 * B_U4 + e) * 16u),
                                "l"(src + e) : "memory");
            }
            asm volatile("cp.async.commit_group;" ::: "memory");
        }

        const uint4* Bb = Bs + (c & 1) * B_U4;
        float acc[8][4];
        #pragma unroll
        for (int nt = 0; nt < 8; nt++)
            #pragma unroll
            for (int qi = 0; qi < 4; qi++) acc[nt][qi] = 0.f;

        #pragma unroll
        for (int s = 0; s < 8; ++s) {
            uint32_t afr[2][4];
            #pragma unroll
            for (int limb = 0; limb < 2; limb++) {
                uint4 v = As[((s * 8 + mg) * 2 + limb) * 32 + lane];
                afr[limb][0] = v.x; afr[limb][1] = v.y;
                afr[limb][2] = v.z; afr[limb][3] = v.w;
            }
            uint32_t bfr[2][8][2];            // [limb][ntile][2 regs]
            #pragma unroll
            for (int limb = 0; limb < 2; limb++)
                #pragma unroll
                for (int np = 0; np < 4; np++) {
                    uint4 v = Bb[((s * 2 + limb) * 8 + ng * 4 + np) * 32 + lane];
                    bfr[limb][np * 2    ][0] = v.x; bfr[limb][np * 2    ][1] = v.y;
                    bfr[limb][np * 2 + 1][0] = v.z; bfr[limb][np * 2 + 1][1] = v.w;
                }
            // 3 terms: h*h, h*m, m*h (m*m ~ 2^-22 rel: negligible)
            #pragma unroll
            for (int term = 0; term < 3; term++) {
                const int la = TLA[term], lb = TLB[term];
                #pragma unroll
                for (int nt = 0; nt < 8; nt++)
                    mma_f16(acc[nt], afr[la], bfr[lb][nt]);
            }
        }

        // ---- epilogue: d2 = ||c||^2 - 2*dot, strict-< running min (n ascending)
        #pragma unroll
        for (int nt = 0; nt < 8; nt++) {
            int nl = c * 128 + ng * 64 + nt * 8 + 2 * (lane & 3);
            float cv0 = cn[nl], cv1 = cn[nl + 1];
            int n = kb0 + nl;
            float d00 = fmaf(-2.f, acc[nt][0], cv0);
            float d01 = fmaf(-2.f, acc[nt][1], cv1);
            float d10 = fmaf(-2.f, acc[nt][2], cv0);
            float d11 = fmaf(-2.f, acc[nt][3], cv1);
            if (d00 < minv[0]) { minv[0] = d00; mini[0] = n; }
            if (d01 < minv[0]) { minv[0] = d01; mini[0] = n + 1; }
            if (d10 < minv[1]) { minv[1] = d10; mini[1] = n; }
            if (d11 < minv[1]) { minv[1] = d11; mini[1] = n + 1; }
        }
    }

    // ---- cross-thread reduce: 8 candidates per token -> g_cv/g_ci[half]
    __syncthreads();                          // all compute done before smem reuse
    float* rv = reinterpret_cast<float*>(smem4);          // [128][8]
    int*   ri = reinterpret_cast<int*>(rv + 1024);
    #pragma unroll
    for (int rh = 0; rh < 2; rh++) {
        int tok  = mg * 16 + rh * 8 + (lane >> 2);
        int slot = ng * 4 + (lane & 3);
        rv[tok * 8 + slot] = minv[rh];
        ri[tok * 8 + slot] = mini[rh];
    }
    __syncthreads();
    if (tid < 128) {
        float bv = rv[tid * 8];
        int   bi = ri[tid * 8];
        #pragma unroll
        for (int x = 1; x < 8; x++) {
            float v = rv[tid * 8 + x];
            int   k = ri[tid * 8 + x];
            if (v < bv || (v == bv && k < bi)) { bv = v; bi = k; }
        }
        g_cv[half * N_TOK + n0 + tid] = bv;
        g_ci[half * N_TOK + n0 + tid] = bi;
    }
}

// ---------------------------------------------------------------------------
// Kernel 3: gather, smem-transpose version. Block = 32 tokens x full D.
// Loads: warp reads whole cb[idx] rows (row-coalesced, 4 wavefronts/token,
// vs 64/warp in the scattered version). Stores: d-major STG.128.
// Pad = 133 floats/row: phase-2 LDS banks (20g+d) mod 32 all distinct.
// ---------------------------------------------------------------------------
#define GPAD 133
__global__ __launch_bounds__(256, 4)
void vq_gather_kernel(const float* __restrict__ cb, float* __restrict__ out) {
    __shared__ float zt[32 * GPAD];
    __shared__ int   ridx[32];

    const int tid  = threadIdx.x;
    const int lane = tid & 31;
    const int wp   = tid >> 5;
    const int tg0  = blockIdx.x * 32;          // first token
    const int b    = tg0 >> 12;
    const int t0   = tg0 & (T_DIM - 1);

    // merge split-K halves (half0 wins ties: half0 indices < half1)
    if (tid < 32) {
        int tg = tg0 + tid;
        float v0 = g_cv[tg], v1 = g_cv[N_TOK + tg];
        ridx[tid] = (v1 < v0) ? g_ci[N_TOK + tg] : g_ci[tg];
    }
    __syncthreads();

    // phase 1: warp wp loads token rows wp*4..wp*4+3 (coalesced 512B each)
    #pragma unroll
    for (int j = 0; j < 4; ++j) {
        int tt = wp * 4 + j;
        const float4* src = reinterpret_cast<const float4*>(
            cb + (size_t)ridx[tt] * D_DIM) + lane;
        float4 v = __ldg(src);
        float* dst = zt + tt * GPAD + lane * 4;
        dst[0] = v.x; dst[1] = v.y; dst[2] = v.z; dst[3] = v.w;
    }
    __syncthreads();

    // phase 2: d-major writes, STG.128 over 4 consecutive t
    #pragma unroll
    for (int i = 0; i < 4; ++i) {
        int e = i * 256 + tid;                 // 1024 float4s
        int d = e >> 3;
        int g = e & 7;
        float4 v;
        v.x = zt[(g * 4 + 0) * GPAD + d];
        v.y = zt[(g * 4 + 1) * GPAD + d];
        v.z = zt[(g * 4 + 2) * GPAD + d];
        v.w = zt[(g * 4 + 3) * GPAD + d];
        size_t o = ((size_t)(b * D_DIM + d)) * T_DIM + t0 + g * 4;
        *reinterpret_cast<float4*>(out + o) = v;
    }
}

// ---------------------------------------------------------------------------
extern "C" void kernel_launch(void* const* d_in, const int* in_sizes, int n_in,
                              void* d_out, int out_size) {
    const float* z  = (const float*)d_in[0];
    const float* cb = (const float*)d_in[1];
    float* out = (float*)d_out;

    cudaFuncSetAttribute(vq_argmin_kernel,
                         cudaFuncAttributeMaxDynamicSharedMemorySize, SMEM_BYTES);

    vq_pre_kernel<<<640, 256>>>(cb);
    vq_argmin_kernel<<<(N_TOK / 128) * 2, 512, SMEM_BYTES>>>(z);
    vq_gather_kernel<<<N_TOK / 32, 256>>>(cb, out);
}